// round 4
// baseline (speedup 1.0000x reference)
#include <cuda_runtime.h>
#include <math.h>
#include <stdint.h>

#define NTOK 4096      // B*S
#define HDIM 1024
#define IDIM 3584
#define NEXP 8

#define KCH  16
#define STG  4
// smem strides / sizes in 32-bit words
#define A_STR    20
#define A_STG_W  (128 * A_STR)   // 2560
#define B1_STR   72              // ffn1 B tile: 16 k-rows x 64 n (+8 pad)
#define B1_STG_W (16 * B1_STR)   // 1152
#define B2_STR   136             // ffn2 B tile: 16 k-rows x 128 n (+8 pad)
#define B2_STG_W (16 * B2_STR)   // 2176

// ---------------- device scratch (no allocs) ----------------
__device__ int   g_cnt[NEXP];
__device__ int   g_tok[NEXP][NTOK];
__device__ float g_wt [NEXP][NTOK];
__device__ int   g_texp [NTOK * 2];
__device__ int   g_tslot[NTOK * 2];
__device__ float g_act [(size_t)NEXP * NTOK * IDIM];
__device__ float g_part[(size_t)NEXP * NTOK * HDIM];

// ---------------- helpers ----------------
__device__ __forceinline__ uint32_t smem_u32(const void* p) {
    uint32_t a;
    asm("{ .reg .u64 t; cvta.to.shared.u64 t, %1; cvt.u32.u64 %0, t; }" : "=r"(a) : "l"(p));
    return a;
}
__device__ __forceinline__ uint32_t f2tf(float f) {
    uint32_t r; asm("cvt.rna.tf32.f32 %0, %1;" : "=r"(r) : "f"(f)); return r;
}
__device__ __forceinline__ void cpa16(uint32_t dst, const float* src) {
    asm volatile("cp.async.cg.shared.global [%0], [%1], 16;" :: "r"(dst), "l"(src));
}
#define CP_COMMIT() asm volatile("cp.async.commit_group;" ::: "memory")
#define CP_WAIT2()  asm volatile("cp.async.wait_group 2;" ::: "memory")

__device__ __forceinline__ void mma8(float* d, uint32_t a0, uint32_t a1, uint32_t a2,
                                     uint32_t a3, uint32_t b0, uint32_t b1) {
    asm volatile(
        "mma.sync.aligned.m16n8k8.row.col.f32.tf32.tf32.f32 "
        "{%0,%1,%2,%3},{%4,%5,%6,%7},{%8,%9},{%0,%1,%2,%3};"
        : "+f"(d[0]), "+f"(d[1]), "+f"(d[2]), "+f"(d[3])
        : "r"(a0), "r"(a1), "r"(a2), "r"(a3), "r"(b0), "r"(b1));
}

// ---------------------------------------------------------------------------
__global__ void zero_kernel() { if (threadIdx.x < NEXP) g_cnt[threadIdx.x] = 0; }

// ---------------------------------------------------------------------------
__global__ void router_kernel(const float* __restrict__ x,
                              const float* __restrict__ gw,
                              float* __restrict__ logits_out) {
    int t = blockIdx.x;
    __shared__ float xs[HDIM];
    __shared__ float lg[NEXP];
    int tid = threadIdx.x;
    for (int i = tid; i < HDIM; i += 256) xs[i] = x[(size_t)t * HDIM + i];
    __syncthreads();
    int w = tid >> 5, lane = tid & 31;
    float s = 0.f;
    for (int k = lane; k < HDIM; k += 32) s += xs[k] * gw[k * NEXP + w];
    #pragma unroll
    for (int o = 16; o; o >>= 1) s += __shfl_xor_sync(0xffffffffu, s, o);
    if (lane == 0) lg[w] = s;
    __syncthreads();
    if (tid == 0) {
        #pragma unroll
        for (int e = 0; e < NEXP; e++) logits_out[(size_t)t * NEXP + e] = lg[e];
        int b0 = 0; float v0 = lg[0];
        #pragma unroll
        for (int e = 1; e < NEXP; e++) if (lg[e] > v0) { v0 = lg[e]; b0 = e; }
        int b1 = -1; float v1 = -INFINITY;
        #pragma unroll
        for (int e = 0; e < NEXP; e++) if (e != b0 && lg[e] > v1) { v1 = lg[e]; b1 = e; }
        float p1  = expf(v1 - v0);
        float inv = 1.0f / (1.0f + p1);
        int p = atomicAdd(&g_cnt[b0], 1);
        g_tok[b0][p] = t; g_wt[b0][p] = inv;
        int q = atomicAdd(&g_cnt[b1], 1);
        g_tok[b1][q] = t; g_wt[b1][q] = p1 * inv;
        g_texp[2 * t] = b0;  g_tslot[2 * t] = p;
        g_texp[2 * t + 1] = b1; g_tslot[2 * t + 1] = q;
    }
}

// ---------------------------------------------------------------------------
// FFN1: CTA tile 128(M gathered) x 64(N) x K; warps 4Mx2N, warp tile 32x32.
// D1=X.w1, D3=X.w3 simultaneously (A-frags shared); G = silu(D1)*D3.
// 4-stage cp.async pipeline, K-chunk 16, 2 CTAs/SM.
// ---------------------------------------------------------------------------
__global__ __launch_bounds__(256, 2)
void ffn1_mma(const float* __restrict__ x,
              const float* __restrict__ w1,
              const float* __restrict__ w3) {
    extern __shared__ float smf[];
    __shared__ int toks[128];
    const int tid = threadIdx.x;
    const int e   = blockIdx.z;
    const int cnt = g_cnt[e];
    const int m0  = blockIdx.y * 128;
    if (m0 >= cnt) return;
    const int n0  = blockIdx.x * 64;

    if (tid < 128) {
        int r = m0 + tid;
        toks[tid] = (r < cnt) ? g_tok[e][r] : g_tok[e][0];
    }
    __syncthreads();
    const uint32_t sb = smem_u32(smf);

    // cp.async source pointers
    // A: 512 16B chunks/stage; thread handles idx=tid, tid+256. row=idx>>2, f=idx&3
    const int fA = tid & 3;
    const int rA0 = tid >> 2, rA1 = (tid + 256) >> 2;
    const float* pA0 = x + (size_t)toks[rA0] * HDIM + fA * 4;
    const float* pA1 = x + (size_t)toks[rA1] * HDIM + fA * 4;
    const uint32_t dA0 = (rA0 * A_STR + fA * 4) * 4;
    const uint32_t dA1 = (rA1 * A_STR + fA * 4) * 4;
    // B: 256 chunks/stage per matrix; row=tid>>4, f=tid&15
    const int rB = tid >> 4, fB = tid & 15;
    const float* pW1 = w1 + (size_t)e * HDIM * IDIM + (size_t)rB * IDIM + n0 + fB * 4;
    const float* pW3 = w3 + (size_t)e * HDIM * IDIM + (size_t)rB * IDIM + n0 + fB * 4;
    const uint32_t dB = (rB * B1_STR + fB * 4) * 4;
    const uint32_t sbB1 = sb + (STG * A_STG_W) * 4;
    const uint32_t sbB3 = sb + (STG * A_STG_W + STG * B1_STG_W) * 4;

    // compute mapping: warps 4Mx2N, warp tile 32x32
    const int wid = tid >> 5, lane = tid & 31;
    const int wm = (wid >> 1) * 32, wn = (wid & 1) * 32;
    const int g = lane >> 2, t = lane & 3;

    float acc1[2][4][4], acc3[2][4][4];
    #pragma unroll
    for (int i = 0; i < 2; i++)
        #pragma unroll
        for (int j = 0; j < 4; j++)
            #pragma unroll
            for (int c = 0; c < 4; c++) { acc1[i][j][c] = 0.f; acc3[i][j][c] = 0.f; }

    const int NC = HDIM / KCH;   // 64
    // prologue: stages 0..2
    #pragma unroll
    for (int s = 0; s < STG - 1; s++) {
        int k0 = s * KCH;
        uint32_t aB = sb + (s * A_STG_W) * 4;
        cpa16(aB + dA0, pA0 + k0);
        cpa16(aB + dA1, pA1 + k0);
        cpa16(sbB1 + (s * B1_STG_W) * 4 + dB, pW1 + (size_t)k0 * IDIM);
        cpa16(sbB3 + (s * B1_STG_W) * 4 + dB, pW3 + (size_t)k0 * IDIM);
        CP_COMMIT();
    }

    for (int it = 0; it < NC; it++) {
        CP_WAIT2();
        __syncthreads();
        int st = it & 3;
        const float* As  = smf + st * A_STG_W;
        const float* B1s = smf + STG * A_STG_W + st * B1_STG_W;
        const float* B3s = smf + STG * A_STG_W + STG * B1_STG_W + st * B1_STG_W;
        #pragma unroll
        for (int ks = 0; ks < 2; ks++) {
            uint32_t af[2][4];
            #pragma unroll
            for (int mt = 0; mt < 2; mt++) {
                int m = wm + mt * 16;
                af[mt][0] = f2tf(As[(m + g)     * A_STR + ks * 8 + t]);
                af[mt][1] = f2tf(As[(m + g + 8) * A_STR + ks * 8 + t]);
                af[mt][2] = f2tf(As[(m + g)     * A_STR + ks * 8 + t + 4]);
                af[mt][3] = f2tf(As[(m + g + 8) * A_STR + ks * 8 + t + 4]);
            }
            #pragma unroll
            for (int nt = 0; nt < 4; nt++) {
                int n = wn + nt * 8;
                uint32_t b10 = f2tf(B1s[(ks * 8 + t)     * B1_STR + n + g]);
                uint32_t b11 = f2tf(B1s[(ks * 8 + t + 4) * B1_STR + n + g]);
                uint32_t b30 = f2tf(B3s[(ks * 8 + t)     * B1_STR + n + g]);
                uint32_t b31 = f2tf(B3s[(ks * 8 + t + 4) * B1_STR + n + g]);
                #pragma unroll
                for (int mt = 0; mt < 2; mt++) {
                    mma8(acc1[mt][nt], af[mt][0], af[mt][1], af[mt][2], af[mt][3], b10, b11);
                    mma8(acc3[mt][nt], af[mt][0], af[mt][1], af[mt][2], af[mt][3], b30, b31);
                }
            }
        }
        int nit = it + STG - 1;
        if (nit < NC) {
            int k0 = nit * KCH, ns = nit & 3;
            uint32_t aB = sb + (ns * A_STG_W) * 4;
            cpa16(aB + dA0, pA0 + k0);
            cpa16(aB + dA1, pA1 + k0);
            cpa16(sbB1 + (ns * B1_STG_W) * 4 + dB, pW1 + (size_t)k0 * IDIM);
            cpa16(sbB3 + (ns * B1_STG_W) * 4 + dB, pW3 + (size_t)k0 * IDIM);
        }
        CP_COMMIT();
    }

    // epilogue: G = silu(D1) * D3
    #pragma unroll
    for (int mt = 0; mt < 2; mt++) {
        int r0 = wm + mt * 16 + g;
        int r1 = r0 + 8;
        bool ok0 = (m0 + r0) < cnt, ok1 = (m0 + r1) < cnt;
        float* G0 = g_act + ((size_t)e * NTOK + m0 + r0) * IDIM + n0;
        float* G1 = g_act + ((size_t)e * NTOK + m0 + r1) * IDIM + n0;
        #pragma unroll
        for (int nt = 0; nt < 4; nt++) {
            int cc = wn + nt * 8 + 2 * t;
            if (ok0) {
                float v0 = acc1[mt][nt][0], v1 = acc1[mt][nt][1];
                float2 o;
                o.x = v0 / (1.0f + __expf(-v0)) * acc3[mt][nt][0];
                o.y = v1 / (1.0f + __expf(-v1)) * acc3[mt][nt][1];
                *(float2*)(G0 + cc) = o;
            }
            if (ok1) {
                float v2 = acc1[mt][nt][2], v3 = acc1[mt][nt][3];
                float2 o;
                o.x = v2 / (1.0f + __expf(-v2)) * acc3[mt][nt][2];
                o.y = v3 / (1.0f + __expf(-v3)) * acc3[mt][nt][3];
                *(float2*)(G1 + cc) = o;
            }
        }
    }
}

// ---------------------------------------------------------------------------
// FFN2: CTA tile 128x128xK; warps 2Mx4N, warp tile 64x32. P = wt*(G.w2).
// ---------------------------------------------------------------------------
__global__ __launch_bounds__(256, 2)
void ffn2_mma(const float* __restrict__ w2) {
    extern __shared__ float smf[];
    __shared__ float wts[128];
    const int tid = threadIdx.x;
    const int e   = blockIdx.z;
    const int cnt = g_cnt[e];
    const int m0  = blockIdx.y * 128;
    if (m0 >= cnt) return;
    const int n0  = blockIdx.x * 128;

    if (tid < 128) {
        int r = m0 + tid;
        wts[tid] = (r < cnt) ? g_wt[e][r] : 0.0f;
    }
    __syncthreads();
    const uint32_t sb = smem_u32(smf);

    const float* A0 = g_act + ((size_t)e * NTOK + m0) * IDIM;
    const int fA = tid & 3;
    const int rA0 = tid >> 2, rA1 = (tid + 256) >> 2;
    const float* pA0 = A0 + (size_t)rA0 * IDIM + fA * 4;
    const float* pA1 = A0 + (size_t)rA1 * IDIM + fA * 4;
    const uint32_t dA0 = (rA0 * A_STR + fA * 4) * 4;
    const uint32_t dA1 = (rA1 * A_STR + fA * 4) * 4;
    // B: 512 chunks/stage: idx=tid, tid+256; row=idx>>5, f=idx&31
    const int rB0 = tid >> 5, rB1i = (tid + 256) >> 5;
    const int fB0 = tid & 31, fB1 = (tid + 256) & 31;
    const float* Wb = w2 + (size_t)e * IDIM * HDIM + n0;
    const float* pB0 = Wb + (size_t)rB0 * HDIM + fB0 * 4;
    const float* pB1 = Wb + (size_t)rB1i * HDIM + fB1 * 4;
    const uint32_t dB0 = (rB0 * B2_STR + fB0 * 4) * 4;
    const uint32_t dB1 = (rB1i * B2_STR + fB1 * 4) * 4;
    const uint32_t sbB = sb + (STG * A_STG_W) * 4;

    const int wid = tid >> 5, lane = tid & 31;
    const int wm = (wid >> 2) * 64, wn = (wid & 3) * 32;
    const int g = lane >> 2, t = lane & 3;

    float acc[4][4][4];
    #pragma unroll
    for (int i = 0; i < 4; i++)
        #pragma unroll
        for (int j = 0; j < 4; j++)
            #pragma unroll
            for (int c = 0; c < 4; c++) acc[i][j][c] = 0.f;

    const int NC = IDIM / KCH;   // 224
    #pragma unroll
    for (int s = 0; s < STG - 1; s++) {
        int k0 = s * KCH;
        uint32_t aB = sb + (s * A_STG_W) * 4;
        uint32_t bB = sbB + (s * B2_STG_W) * 4;
        cpa16(aB + dA0, pA0 + k0);
        cpa16(aB + dA1, pA1 + k0);
        cpa16(bB + dB0, pB0 + (size_t)k0 * HDIM);
        cpa16(bB + dB1, pB1 + (size_t)k0 * HDIM);
        CP_COMMIT();
    }

    for (int it = 0; it < NC; it++) {
        CP_WAIT2();
        __syncthreads();
        int st = it & 3;
        const float* As = smf + st * A_STG_W;
        const float* Bs = smf + STG * A_STG_W + st * B2_STG_W;
        #pragma unroll
        for (int ks = 0; ks < 2; ks++) {
            uint32_t af[4][4];
            #pragma unroll
            for (int mt = 0; mt < 4; mt++) {
                int m = wm + mt * 16;
                af[mt][0] = f2tf(As[(m + g)     * A_STR + ks * 8 + t]);
                af[mt][1] = f2tf(As[(m + g + 8) * A_STR + ks * 8 + t]);
                af[mt][2] = f2tf(As[(m + g)     * A_STR + ks * 8 + t + 4]);
                af[mt][3] = f2tf(As[(m + g + 8) * A_STR + ks * 8 + t + 4]);
            }
            #pragma unroll
            for (int nt = 0; nt < 4; nt++) {
                int n = wn + nt * 8;
                uint32_t b0 = f2tf(Bs[(ks * 8 + t)     * B2_STR + n + g]);
                uint32_t b1 = f2tf(Bs[(ks * 8 + t + 4) * B2_STR + n + g]);
                #pragma unroll
                for (int mt = 0; mt < 4; mt++)
                    mma8(acc[mt][nt], af[mt][0], af[mt][1], af[mt][2], af[mt][3], b0, b1);
            }
        }
        int nit = it + STG - 1;
        if (nit < NC) {
            int k0 = nit * KCH, ns = nit & 3;
            uint32_t aB = sb + (ns * A_STG_W) * 4;
            uint32_t bB = sbB + (ns * B2_STG_W) * 4;
            cpa16(aB + dA0, pA0 + k0);
            cpa16(aB + dA1, pA1 + k0);
            cpa16(bB + dB0, pB0 + (size_t)k0 * HDIM);
            cpa16(bB + dB1, pB1 + (size_t)k0 * HDIM);
        }
        CP_COMMIT();
    }

    #pragma unroll
    for (int mt = 0; mt < 4; mt++) {
        int r0 = wm + mt * 16 + g;
        int r1 = r0 + 8;
        bool ok0 = (m0 + r0) < cnt, ok1 = (m0 + r1) < cnt;
        float w0 = wts[r0], w1v = wts[r1];
        float* P0 = g_part + ((size_t)e * NTOK + m0 + r0) * HDIM + n0;
        float* P1 = g_part + ((size_t)e * NTOK + m0 + r1) * HDIM + n0;
        #pragma unroll
        for (int nt = 0; nt < 4; nt++) {
            int cc = wn + nt * 8 + 2 * t;
            if (ok0) *(float2*)(P0 + cc) = make_float2(w0 * acc[mt][nt][0], w0 * acc[mt][nt][1]);
            if (ok1) *(float2*)(P1 + cc) = make_float2(w1v * acc[mt][nt][2], w1v * acc[mt][nt][3]);
        }
    }
}

// ---------------------------------------------------------------------------
__global__ void combine_kernel(float* __restrict__ out) {
    int t  = blockIdx.x;
    int e0 = g_texp[2 * t],     s0 = g_tslot[2 * t];
    int e1 = g_texp[2 * t + 1], s1 = g_tslot[2 * t + 1];
    const float4* P0 = (const float4*)(g_part + ((size_t)e0 * NTOK + s0) * HDIM);
    const float4* P1 = (const float4*)(g_part + ((size_t)e1 * NTOK + s1) * HDIM);
    float4* O = (float4*)(out + (size_t)t * HDIM);
    int i = threadIdx.x;
    float4 a = P0[i], b = P1[i];
    O[i] = make_float4(a.x + b.x, a.y + b.y, a.z + b.z, a.w + b.w);
}

// ---------------------------------------------------------------------------
extern "C" void kernel_launch(void* const* d_in, const int* in_sizes, int n_in,
                              void* d_out, int out_size) {
    const float* x  = (const float*)d_in[0];
    const float* gw = (const float*)d_in[1];
    const float* w1 = (const float*)d_in[2];
    const float* w3 = (const float*)d_in[3];
    const float* w2 = (const float*)d_in[4];
    float* out = (float*)d_out;
    float* logits = out + ((size_t)out_size - (size_t)NTOK * NEXP);

    const int SMEM1 = (STG * A_STG_W + 2 * STG * B1_STG_W) * 4;  // 77824 B
    const int SMEM2 = (STG * A_STG_W + STG * B2_STG_W) * 4;      // 75776 B
    cudaFuncSetAttribute(ffn1_mma, cudaFuncAttributeMaxDynamicSharedMemorySize, SMEM1);
    cudaFuncSetAttribute(ffn2_mma, cudaFuncAttributeMaxDynamicSharedMemorySize, SMEM2);

    zero_kernel<<<1, 32>>>();
    router_kernel<<<NTOK, 256>>>(x, gw, logits);

    dim3 g1(IDIM / 64, NTOK / 128, NEXP);
    ffn1_mma<<<g1, 256, SMEM1>>>(x, w1, w3);

    dim3 g2(HDIM / 128, NTOK / 128, NEXP);
    ffn2_mma<<<g2, 256, SMEM2>>>(w2);

    combine_kernel<<<NTOK, 256>>>(out);
}

// round 5
// speedup vs baseline: 1.3769x; 1.3769x over previous
#include <cuda_runtime.h>
#include <math.h>
#include <stdint.h>

#define NTOK 4096      // B*S
#define HDIM 1024
#define IDIM 3584
#define NEXP 8

// smem strides in 32-bit words (tf32 data stored at STS time)
#define ASTR 36    // 128 rows x 32 k (+4 pad)
#define BSTR 136   // 32 k-rows x 128 n (+8 pad)
#define A_WORDS  (128 * ASTR)   // 4608
#define B_WORDS  (32 * BSTR)    // 4352

// ---------------- device scratch (no allocs) ----------------
__device__ int   g_cnt[NEXP];
__device__ int   g_tok[NEXP][NTOK];
__device__ float g_wt [NEXP][NTOK];
__device__ int   g_texp [NTOK * 2];
__device__ int   g_tslot[NTOK * 2];
__device__ float g_act [(size_t)NEXP * NTOK * IDIM];
__device__ float g_part[(size_t)NEXP * NTOK * HDIM];

// ---------------- helpers ----------------
__device__ __forceinline__ uint32_t smem_u32(const void* p) {
    uint32_t a;
    asm("{ .reg .u64 t; cvta.to.shared.u64 t, %1; cvt.u32.u64 %0, t; }" : "=r"(a) : "l"(p));
    return a;
}
__device__ __forceinline__ uint32_t f2tf(float f) {
    uint32_t r; asm("cvt.rna.tf32.f32 %0, %1;" : "=r"(r) : "f"(f)); return r;
}
__device__ __forceinline__ void sts_tf4(uint32_t addr, float4 v) {
    uint32_t a = f2tf(v.x), b = f2tf(v.y), c = f2tf(v.z), d = f2tf(v.w);
    asm volatile("st.shared.v4.b32 [%0], {%1,%2,%3,%4};"
                 :: "r"(addr), "r"(a), "r"(b), "r"(c), "r"(d) : "memory");
}
__device__ __forceinline__ void mma8(float* d, uint32_t a0, uint32_t a1, uint32_t a2,
                                     uint32_t a3, uint32_t b0, uint32_t b1) {
    asm volatile(
        "mma.sync.aligned.m16n8k8.row.col.f32.tf32.tf32.f32 "
        "{%0,%1,%2,%3},{%4,%5,%6,%7},{%8,%9},{%0,%1,%2,%3};"
        : "+f"(d[0]), "+f"(d[1]), "+f"(d[2]), "+f"(d[3])
        : "r"(a0), "r"(a1), "r"(a2), "r"(a3), "r"(b0), "r"(b1));
}

// ---------------------------------------------------------------------------
__global__ void zero_kernel() { if (threadIdx.x < NEXP) g_cnt[threadIdx.x] = 0; }

// ---------------------------------------------------------------------------
__global__ void router_kernel(const float* __restrict__ x,
                              const float* __restrict__ gw,
                              float* __restrict__ logits_out) {
    int t = blockIdx.x;
    __shared__ float xs[HDIM];
    __shared__ float lg[NEXP];
    int tid = threadIdx.x;
    for (int i = tid; i < HDIM; i += 256) xs[i] = x[(size_t)t * HDIM + i];
    __syncthreads();
    int w = tid >> 5, lane = tid & 31;
    float s = 0.f;
    for (int k = lane; k < HDIM; k += 32) s += xs[k] * gw[k * NEXP + w];
    #pragma unroll
    for (int o = 16; o; o >>= 1) s += __shfl_xor_sync(0xffffffffu, s, o);
    if (lane == 0) lg[w] = s;
    __syncthreads();
    if (tid == 0) {
        #pragma unroll
        for (int e = 0; e < NEXP; e++) logits_out[(size_t)t * NEXP + e] = lg[e];
        int b0 = 0; float v0 = lg[0];
        #pragma unroll
        for (int e = 1; e < NEXP; e++) if (lg[e] > v0) { v0 = lg[e]; b0 = e; }
        int b1 = -1; float v1 = -INFINITY;
        #pragma unroll
        for (int e = 0; e < NEXP; e++) if (e != b0 && lg[e] > v1) { v1 = lg[e]; b1 = e; }
        float p1  = expf(v1 - v0);
        float inv = 1.0f / (1.0f + p1);
        int p = atomicAdd(&g_cnt[b0], 1);
        g_tok[b0][p] = t; g_wt[b0][p] = inv;
        int q = atomicAdd(&g_cnt[b1], 1);
        g_tok[b1][q] = t; g_wt[b1][q] = p1 * inv;
        g_texp[2 * t] = b0;  g_tslot[2 * t] = p;
        g_texp[2 * t + 1] = b1; g_tslot[2 * t + 1] = q;
    }
}

// ---------------------------------------------------------------------------
// FFN1: CTA 128(M gathered) x 128(N) x K32; 512 thr = 16 warps (4Mx4N),
// warp tile 32x32, dual outputs D1/D3 with shared A frags. G = silu(D1)*D3.
// ---------------------------------------------------------------------------
__global__ __launch_bounds__(512)
void ffn1_mma(const float* __restrict__ x,
              const float* __restrict__ w1,
              const float* __restrict__ w3) {
    extern __shared__ uint32_t sm[];
    __shared__ int toks[128];
    const int tid = threadIdx.x;
    const int e   = blockIdx.z;
    const int cnt = g_cnt[e];
    const int m0  = blockIdx.y * 128;
    if (m0 >= cnt) return;
    const int n0  = blockIdx.x * 128;

    if (tid < 128) {
        int r = m0 + tid;
        toks[tid] = (r < cnt) ? g_tok[e][r] : g_tok[e][0];
    }
    __syncthreads();
    const uint32_t sb = smem_u32(sm);

    // staging: A 1024 float4/chunk -> 2/thread; B each 1024 -> 2/thread
    const int fa = tid & 7,  ra = tid >> 3;     // ra 0..63 -> rows ra, ra+64
    const int fb = tid & 31, kb = tid >> 5;     // kb 0..15 -> k-rows kb, kb+16
    const float* ap0 = x + (size_t)toks[ra]      * HDIM + fa * 4;
    const float* ap1 = x + (size_t)toks[ra + 64] * HDIM + fa * 4;
    const float* W1 = w1 + (size_t)e * HDIM * IDIM + n0 + fb * 4;
    const float* W3 = w3 + (size_t)e * HDIM * IDIM + n0 + fb * 4;
    const uint32_t dA0 = (ra * ASTR + fa * 4) * 4;
    const uint32_t dA1 = ((ra + 64) * ASTR + fa * 4) * 4;
    const uint32_t dB0 = (kb * BSTR + fb * 4) * 4;
    const uint32_t dB1 = ((kb + 16) * BSTR + fb * 4) * 4;

    // compute mapping: 16 warps, 4Mx4N, warp tile 32x32
    const int wid = tid >> 5, lane = tid & 31;
    const int wm = (wid >> 2) * 32, wn = (wid & 3) * 32;
    const int g = lane >> 2, t = lane & 3;

    float acc1[2][4][4], acc3[2][4][4];
    #pragma unroll
    for (int i = 0; i < 2; i++)
        #pragma unroll
        for (int j = 0; j < 4; j++)
            #pragma unroll
            for (int c = 0; c < 4; c++) { acc1[i][j][c] = 0.f; acc3[i][j][c] = 0.f; }

    float4 rA0, rA1, rW1a, rW1b, rW3a, rW3b;
    rA0  = *(const float4*)(ap0);
    rA1  = *(const float4*)(ap1);
    rW1a = *(const float4*)(W1 + (size_t)kb * IDIM);
    rW1b = *(const float4*)(W1 + (size_t)(kb + 16) * IDIM);
    rW3a = *(const float4*)(W3 + (size_t)kb * IDIM);
    rW3b = *(const float4*)(W3 + (size_t)(kb + 16) * IDIM);

    const int NC = HDIM / 32;   // 32
    for (int it = 0; it < NC; it++) {
        int p = it & 1;
        uint32_t aoff  = sb + (p * A_WORDS) * 4;
        uint32_t b1off = sb + (2 * A_WORDS + p * B_WORDS) * 4;
        uint32_t b3off = sb + (2 * A_WORDS + 2 * B_WORDS + p * B_WORDS) * 4;
        sts_tf4(aoff + dA0, rA0);
        sts_tf4(aoff + dA1, rA1);
        sts_tf4(b1off + dB0, rW1a);
        sts_tf4(b1off + dB1, rW1b);
        sts_tf4(b3off + dB0, rW3a);
        sts_tf4(b3off + dB1, rW3b);
        __syncthreads();
        if (it + 1 < NC) {
            int k0 = (it + 1) * 32;
            rA0  = *(const float4*)(ap0 + k0);
            rA1  = *(const float4*)(ap1 + k0);
            rW1a = *(const float4*)(W1 + (size_t)(k0 + kb) * IDIM);
            rW1b = *(const float4*)(W1 + (size_t)(k0 + kb + 16) * IDIM);
            rW3a = *(const float4*)(W3 + (size_t)(k0 + kb) * IDIM);
            rW3b = *(const float4*)(W3 + (size_t)(k0 + kb + 16) * IDIM);
        }
        const uint32_t* As  = sm + p * A_WORDS;
        const uint32_t* B1s = sm + 2 * A_WORDS + p * B_WORDS;
        const uint32_t* B3s = sm + 2 * A_WORDS + 2 * B_WORDS + p * B_WORDS;
        #pragma unroll
        for (int ks = 0; ks < 4; ks++) {
            uint32_t af[2][4];
            #pragma unroll
            for (int mt = 0; mt < 2; mt++) {
                int m = wm + mt * 16;
                af[mt][0] = As[(m + g)     * ASTR + ks * 8 + t];
                af[mt][1] = As[(m + g + 8) * ASTR + ks * 8 + t];
                af[mt][2] = As[(m + g)     * ASTR + ks * 8 + t + 4];
                af[mt][3] = As[(m + g + 8) * ASTR + ks * 8 + t + 4];
            }
            #pragma unroll
            for (int nt = 0; nt < 4; nt++) {
                int n = wn + nt * 8;
                uint32_t b10 = B1s[(ks * 8 + t)     * BSTR + n + g];
                uint32_t b11 = B1s[(ks * 8 + t + 4) * BSTR + n + g];
                uint32_t b30 = B3s[(ks * 8 + t)     * BSTR + n + g];
                uint32_t b31 = B3s[(ks * 8 + t + 4) * BSTR + n + g];
                #pragma unroll
                for (int mt = 0; mt < 2; mt++) {
                    mma8(acc1[mt][nt], af[mt][0], af[mt][1], af[mt][2], af[mt][3], b10, b11);
                    mma8(acc3[mt][nt], af[mt][0], af[mt][1], af[mt][2], af[mt][3], b30, b31);
                }
            }
        }
    }

    // epilogue: G = silu(D1) * D3
    #pragma unroll
    for (int mt = 0; mt < 2; mt++) {
        int r0 = wm + mt * 16 + g;
        int r1 = r0 + 8;
        bool ok0 = (m0 + r0) < cnt, ok1 = (m0 + r1) < cnt;
        float* G0 = g_act + ((size_t)e * NTOK + m0 + r0) * IDIM + n0;
        float* G1 = g_act + ((size_t)e * NTOK + m0 + r1) * IDIM + n0;
        #pragma unroll
        for (int nt = 0; nt < 4; nt++) {
            int cc = wn + nt * 8 + 2 * t;
            if (ok0) {
                float v0 = acc1[mt][nt][0], v1 = acc1[mt][nt][1];
                float2 o;
                o.x = v0 / (1.0f + __expf(-v0)) * acc3[mt][nt][0];
                o.y = v1 / (1.0f + __expf(-v1)) * acc3[mt][nt][1];
                *(float2*)(G0 + cc) = o;
            }
            if (ok1) {
                float v2 = acc1[mt][nt][2], v3 = acc1[mt][nt][3];
                float2 o;
                o.x = v2 / (1.0f + __expf(-v2)) * acc3[mt][nt][2];
                o.y = v3 / (1.0f + __expf(-v3)) * acc3[mt][nt][3];
                *(float2*)(G1 + cc) = o;
            }
        }
    }
}

// ---------------------------------------------------------------------------
// FFN2: CTA 128x128xK32; 512 thr, 16 warps (4Mx4N), warp tile 32x32.
// P = wt * (G . w2), weight folded, no atomics.
// ---------------------------------------------------------------------------
__global__ __launch_bounds__(512)
void ffn2_mma(const float* __restrict__ w2) {
    extern __shared__ uint32_t sm[];
    __shared__ float wts[128];
    const int tid = threadIdx.x;
    const int e   = blockIdx.z;
    const int cnt = g_cnt[e];
    const int m0  = blockIdx.y * 128;
    if (m0 >= cnt) return;
    const int n0  = blockIdx.x * 128;

    if (tid < 128) {
        int r = m0 + tid;
        wts[tid] = (r < cnt) ? g_wt[e][r] : 0.0f;
    }
    __syncthreads();
    const uint32_t sb = smem_u32(sm);

    const int fa = tid & 7,  ra = tid >> 3;
    const int fb = tid & 31, kb = tid >> 5;
    const float* A0 = g_act + ((size_t)e * NTOK + m0) * IDIM;
    const float* ap0 = A0 + (size_t)ra * IDIM + fa * 4;
    const float* ap1 = A0 + (size_t)(ra + 64) * IDIM + fa * 4;
    const float* W = w2 + (size_t)e * IDIM * HDIM + n0 + fb * 4;
    const uint32_t dA0 = (ra * ASTR + fa * 4) * 4;
    const uint32_t dA1 = ((ra + 64) * ASTR + fa * 4) * 4;
    const uint32_t dB0 = (kb * BSTR + fb * 4) * 4;
    const uint32_t dB1 = ((kb + 16) * BSTR + fb * 4) * 4;

    const int wid = tid >> 5, lane = tid & 31;
    const int wm = (wid >> 2) * 32, wn = (wid & 3) * 32;
    const int g = lane >> 2, t = lane & 3;

    float acc[2][4][4];
    #pragma unroll
    for (int i = 0; i < 2; i++)
        #pragma unroll
        for (int j = 0; j < 4; j++)
            #pragma unroll
            for (int c = 0; c < 4; c++) acc[i][j][c] = 0.f;

    float4 rA0, rA1, rB0, rB1;
    rA0 = *(const float4*)(ap0);
    rA1 = *(const float4*)(ap1);
    rB0 = *(const float4*)(W + (size_t)kb * HDIM);
    rB1 = *(const float4*)(W + (size_t)(kb + 16) * HDIM);

    const int NC = IDIM / 32;   // 112
    for (int it = 0; it < NC; it++) {
        int p = it & 1;
        uint32_t aoff = sb + (p * A_WORDS) * 4;
        uint32_t boff = sb + (2 * A_WORDS + p * B_WORDS) * 4;
        sts_tf4(aoff + dA0, rA0);
        sts_tf4(aoff + dA1, rA1);
        sts_tf4(boff + dB0, rB0);
        sts_tf4(boff + dB1, rB1);
        __syncthreads();
        if (it + 1 < NC) {
            int k0 = (it + 1) * 32;
            rA0 = *(const float4*)(ap0 + k0);
            rA1 = *(const float4*)(ap1 + k0);
            rB0 = *(const float4*)(W + (size_t)(k0 + kb) * HDIM);
            rB1 = *(const float4*)(W + (size_t)(k0 + kb + 16) * HDIM);
        }
        const uint32_t* As = sm + p * A_WORDS;
        const uint32_t* Bs = sm + 2 * A_WORDS + p * B_WORDS;
        #pragma unroll
        for (int ks = 0; ks < 4; ks++) {
            uint32_t af[2][4];
            #pragma unroll
            for (int mt = 0; mt < 2; mt++) {
                int m = wm + mt * 16;
                af[mt][0] = As[(m + g)     * ASTR + ks * 8 + t];
                af[mt][1] = As[(m + g + 8) * ASTR + ks * 8 + t];
                af[mt][2] = As[(m + g)     * ASTR + ks * 8 + t + 4];
                af[mt][3] = As[(m + g + 8) * ASTR + ks * 8 + t + 4];
            }
            #pragma unroll
            for (int nt = 0; nt < 4; nt++) {
                int n = wn + nt * 8;
                uint32_t b0 = Bs[(ks * 8 + t)     * BSTR + n + g];
                uint32_t b1 = Bs[(ks * 8 + t + 4) * BSTR + n + g];
                #pragma unroll
                for (int mt = 0; mt < 2; mt++)
                    mma8(acc[mt][nt], af[mt][0], af[mt][1], af[mt][2], af[mt][3], b0, b1);
            }
        }
    }

    #pragma unroll
    for (int mt = 0; mt < 2; mt++) {
        int r0 = wm + mt * 16 + g;
        int r1 = r0 + 8;
        bool ok0 = (m0 + r0) < cnt, ok1 = (m0 + r1) < cnt;
        float w0 = wts[r0], w1v = wts[r1];
        float* P0 = g_part + ((size_t)e * NTOK + m0 + r0) * HDIM + n0;
        float* P1 = g_part + ((size_t)e * NTOK + m0 + r1) * HDIM + n0;
        #pragma unroll
        for (int nt = 0; nt < 4; nt++) {
            int cc = wn + nt * 8 + 2 * t;
            if (ok0) *(float2*)(P0 + cc) = make_float2(w0 * acc[mt][nt][0], w0 * acc[mt][nt][1]);
            if (ok1) *(float2*)(P1 + cc) = make_float2(w1v * acc[mt][nt][2], w1v * acc[mt][nt][3]);
        }
    }
}

// ---------------------------------------------------------------------------
__global__ void combine_kernel(float* __restrict__ out) {
    int t  = blockIdx.x;
    int e0 = g_texp[2 * t],     s0 = g_tslot[2 * t];
    int e1 = g_texp[2 * t + 1], s1 = g_tslot[2 * t + 1];
    const float4* P0 = (const float4*)(g_part + ((size_t)e0 * NTOK + s0) * HDIM);
    const float4* P1 = (const float4*)(g_part + ((size_t)e1 * NTOK + s1) * HDIM);
    float4* O = (float4*)(out + (size_t)t * HDIM);
    int i = threadIdx.x;
    float4 a = P0[i], b = P1[i];
    O[i] = make_float4(a.x + b.x, a.y + b.y, a.z + b.z, a.w + b.w);
}

// ---------------------------------------------------------------------------
extern "C" void kernel_launch(void* const* d_in, const int* in_sizes, int n_in,
                              void* d_out, int out_size) {
    const float* x  = (const float*)d_in[0];
    const float* gw = (const float*)d_in[1];
    const float* w1 = (const float*)d_in[2];
    const float* w3 = (const float*)d_in[3];
    const float* w2 = (const float*)d_in[4];
    float* out = (float*)d_out;
    float* logits = out + ((size_t)out_size - (size_t)NTOK * NEXP);

    const int SMEM1 = (2 * A_WORDS + 4 * B_WORDS) * 4;  // 106496 B
    const int SMEM2 = (2 * A_WORDS + 2 * B_WORDS) * 4;  //  71680 B
    cudaFuncSetAttribute(ffn1_mma, cudaFuncAttributeMaxDynamicSharedMemorySize, SMEM1);
    cudaFuncSetAttribute(ffn2_mma, cudaFuncAttributeMaxDynamicSharedMemorySize, SMEM2);

    zero_kernel<<<1, 32>>>();
    router_kernel<<<NTOK, 256>>>(x, gw, logits);

    dim3 g1(IDIM / 128, NTOK / 128, NEXP);
    ffn1_mma<<<g1, 512, SMEM1>>>(x, w1, w3);

    dim3 g2(HDIM / 128, NTOK / 128, NEXP);
    ffn2_mma<<<g2, 512, SMEM2>>>(w2);

    combine_kernel<<<NTOK, 256>>>(out);
}

// round 6
// speedup vs baseline: 2.5244x; 1.8334x over previous
#include <cuda_runtime.h>
#include <cuda_fp16.h>
#include <math.h>
#include <stdint.h>

#define NTOK 4096      // B*S
#define HDIM 1024
#define IDIM 3584
#define NEXP 8

// smem pitches in fp16 halves
#define AP  40    // A tile row: 32 k + 8 pad   (20 words: ldsm rows hit banks 4r%32 pattern - conflict-free)
#define BP1 136   // ffn1 B row: 128 n + 8      (68 words)
#define BP2 264   // ffn2 B row: 256 n + 8      (132 words)
#define A_H   (128 * AP)    // 5120 halves / stage
#define B1_H  (32 * BP1)    // 4352
#define B2_H  (32 * BP2)    // 8448

// ---------------- device scratch (no allocs) ----------------
__device__ int    g_cnt[NEXP];
__device__ int    g_tok[NEXP][NTOK];
__device__ float  g_wt [NEXP][NTOK];
__device__ int    g_texp [NTOK * 2];
__device__ int    g_tslot[NTOK * 2];
__device__ __half g_act [(size_t)NEXP * NTOK * IDIM];   // fp16 activations
__device__ float  g_part[(size_t)NEXP * NTOK * HDIM];   // weight-folded outs

// ---------------- helpers ----------------
__device__ __forceinline__ uint32_t smem_u32(const void* p) {
    uint32_t a;
    asm("{ .reg .u64 t; cvta.to.shared.u64 t, %1; cvt.u32.u64 %0, t; }" : "=r"(a) : "l"(p));
    return a;
}
__device__ __forceinline__ void sts_h4(uint32_t addr, float4 v) {
    __half2 h0 = __floats2half2_rn(v.x, v.y);
    __half2 h1 = __floats2half2_rn(v.z, v.w);
    uint32_t u0 = *reinterpret_cast<uint32_t*>(&h0);
    uint32_t u1 = *reinterpret_cast<uint32_t*>(&h1);
    asm volatile("st.shared.v2.b32 [%0], {%1,%2};" :: "r"(addr), "r"(u0), "r"(u1) : "memory");
}
__device__ __forceinline__ void sts_u2(uint32_t addr, uint2 v) {
    asm volatile("st.shared.v2.b32 [%0], {%1,%2};" :: "r"(addr), "r"(v.x), "r"(v.y) : "memory");
}
__device__ __forceinline__ void ldsm4(uint32_t* r, uint32_t a) {
    asm volatile("ldmatrix.sync.aligned.m8n8.x4.shared.b16 {%0,%1,%2,%3}, [%4];"
                 : "=r"(r[0]), "=r"(r[1]), "=r"(r[2]), "=r"(r[3]) : "r"(a));
}
__device__ __forceinline__ void ldsm4t(uint32_t* r, uint32_t a) {
    asm volatile("ldmatrix.sync.aligned.m8n8.x4.trans.shared.b16 {%0,%1,%2,%3}, [%4];"
                 : "=r"(r[0]), "=r"(r[1]), "=r"(r[2]), "=r"(r[3]) : "r"(a));
}
__device__ __forceinline__ void mma16(float* d, const uint32_t* a, uint32_t b0, uint32_t b1) {
    asm volatile(
        "mma.sync.aligned.m16n8k16.row.col.f32.f16.f16.f32 "
        "{%0,%1,%2,%3},{%4,%5,%6,%7},{%8,%9},{%0,%1,%2,%3};"
        : "+f"(d[0]), "+f"(d[1]), "+f"(d[2]), "+f"(d[3])
        : "r"(a[0]), "r"(a[1]), "r"(a[2]), "r"(a[3]), "r"(b0), "r"(b1));
}

// ---------------------------------------------------------------------------
__global__ void zero_kernel() { if (threadIdx.x < NEXP) g_cnt[threadIdx.x] = 0; }

// ---------------------------------------------------------------------------
__global__ void router_kernel(const float* __restrict__ x,
                              const float* __restrict__ gw,
                              float* __restrict__ logits_out) {
    int t = blockIdx.x;
    __shared__ float xs[HDIM];
    __shared__ float lg[NEXP];
    int tid = threadIdx.x;
    for (int i = tid; i < HDIM; i += 256) xs[i] = x[(size_t)t * HDIM + i];
    __syncthreads();
    int w = tid >> 5, lane = tid & 31;
    float s = 0.f;
    for (int k = lane; k < HDIM; k += 32) s += xs[k] * gw[k * NEXP + w];
    #pragma unroll
    for (int o = 16; o; o >>= 1) s += __shfl_xor_sync(0xffffffffu, s, o);
    if (lane == 0) lg[w] = s;
    __syncthreads();
    if (tid == 0) {
        #pragma unroll
        for (int e = 0; e < NEXP; e++) logits_out[(size_t)t * NEXP + e] = lg[e];
        int b0 = 0; float v0 = lg[0];
        #pragma unroll
        for (int e = 1; e < NEXP; e++) if (lg[e] > v0) { v0 = lg[e]; b0 = e; }
        int b1 = -1; float v1 = -INFINITY;
        #pragma unroll
        for (int e = 0; e < NEXP; e++) if (e != b0 && lg[e] > v1) { v1 = lg[e]; b1 = e; }
        float p1  = expf(v1 - v0);
        float inv = 1.0f / (1.0f + p1);
        int p = atomicAdd(&g_cnt[b0], 1);
        g_tok[b0][p] = t; g_wt[b0][p] = inv;
        int q = atomicAdd(&g_cnt[b1], 1);
        g_tok[b1][q] = t; g_wt[b1][q] = p1 * inv;
        g_texp[2 * t] = b0;  g_tslot[2 * t] = p;
        g_texp[2 * t + 1] = b1; g_tslot[2 * t + 1] = q;
    }
}

// ---------------------------------------------------------------------------
// FFN1: CTA 128(M)x128(N)xK32, 512 thr (16 warps, 4Mx4N), warp 32x32 dual.
// fp16 mma m16n8k16 + ldmatrix; G = silu(X.w1)*(X.w3) stored fp16.
// ---------------------------------------------------------------------------
__global__ __launch_bounds__(512)
void ffn1_mma(const float* __restrict__ x,
              const float* __restrict__ w1,
              const float* __restrict__ w3) {
    extern __shared__ __half smh[];
    __shared__ int toks[128];
    const int tid = threadIdx.x;
    const int e   = blockIdx.z;
    const int cnt = g_cnt[e];
    const int m0  = blockIdx.y * 128;
    if (m0 >= cnt) return;
    const int n0  = blockIdx.x * 128;

    if (tid < 128) {
        int r = m0 + tid;
        toks[tid] = (r < cnt) ? g_tok[e][r] : g_tok[e][0];
    }
    __syncthreads();
    const uint32_t sb = smem_u32(smh);
    // layout: [A s0][A s1][B1 s0][B1 s1][B3 s0][B3 s1]
    const uint32_t oA  = 0;
    const uint32_t oB1 = 2 * A_H * 2;
    const uint32_t oB3 = (2 * A_H + 2 * B1_H) * 2;

    // staging: A 2 float4/thread, B1/B3 2 float4 each
    const int fa = tid & 7,  ra = tid >> 3;
    const int fb = tid & 31, kb = tid >> 5;
    const float* ap0 = x + (size_t)toks[ra]      * HDIM + fa * 4;
    const float* ap1 = x + (size_t)toks[ra + 64] * HDIM + fa * 4;
    const float* W1 = w1 + (size_t)e * HDIM * IDIM + n0 + fb * 4;
    const float* W3 = w3 + (size_t)e * HDIM * IDIM + n0 + fb * 4;
    const uint32_t dA0 = (ra * AP + fa * 4) * 2;
    const uint32_t dA1 = ((ra + 64) * AP + fa * 4) * 2;
    const uint32_t dB0 = (kb * BP1 + fb * 4) * 2;
    const uint32_t dB1 = ((kb + 16) * BP1 + fb * 4) * 2;

    // compute mapping
    const int wid = tid >> 5, lane = tid & 31;
    const int wm = (wid >> 2) * 32, wn = (wid & 3) * 32;
    const int g = lane >> 2, t = lane & 3;
    const int rowoff = (lane & 8) + (lane & 7);
    const int khalf  = (lane & 16) >> 1;    // 0 or 8 halves

    float acc1[2][4][4], acc3[2][4][4];
    #pragma unroll
    for (int i = 0; i < 2; i++)
        #pragma unroll
        for (int j = 0; j < 4; j++)
            #pragma unroll
            for (int c = 0; c < 4; c++) { acc1[i][j][c] = 0.f; acc3[i][j][c] = 0.f; }

    float4 rA0, rA1, r1a, r1b, r3a, r3b;
    rA0 = *(const float4*)(ap0);
    rA1 = *(const float4*)(ap1);
    r1a = *(const float4*)(W1 + (size_t)kb * IDIM);
    r1b = *(const float4*)(W1 + (size_t)(kb + 16) * IDIM);
    r3a = *(const float4*)(W3 + (size_t)kb * IDIM);
    r3b = *(const float4*)(W3 + (size_t)(kb + 16) * IDIM);

    const int NC = HDIM / 32;   // 32
    for (int it = 0; it < NC; it++) {
        int p = it & 1;
        uint32_t aS  = sb + oA  + p * (A_H * 2);
        uint32_t b1S = sb + oB1 + p * (B1_H * 2);
        uint32_t b3S = sb + oB3 + p * (B1_H * 2);
        sts_h4(aS + dA0, rA0);
        sts_h4(aS + dA1, rA1);
        sts_h4(b1S + dB0, r1a);
        sts_h4(b1S + dB1, r1b);
        sts_h4(b3S + dB0, r3a);
        sts_h4(b3S + dB1, r3b);
        __syncthreads();
        if (it + 1 < NC) {
            int k0 = (it + 1) * 32;
            rA0 = *(const float4*)(ap0 + k0);
            rA1 = *(const float4*)(ap1 + k0);
            r1a = *(const float4*)(W1 + (size_t)(k0 + kb) * IDIM);
            r1b = *(const float4*)(W1 + (size_t)(k0 + kb + 16) * IDIM);
            r3a = *(const float4*)(W3 + (size_t)(k0 + kb) * IDIM);
            r3b = *(const float4*)(W3 + (size_t)(k0 + kb + 16) * IDIM);
        }
        #pragma unroll
        for (int ks = 0; ks < 2; ks++) {
            uint32_t a0[4], a1[4];
            ldsm4(a0, aS + ((wm + rowoff) * AP + ks * 16 + khalf) * 2);
            ldsm4(a1, aS + ((wm + 16 + rowoff) * AP + ks * 16 + khalf) * 2);
            #pragma unroll
            for (int j = 0; j < 2; j++) {
                uint32_t br[4];
                uint32_t bo = ((ks * 16 + rowoff) * BP1 + wn + j * 16 + khalf) * 2;
                ldsm4t(br, b1S + bo);
                mma16(acc1[0][2 * j],     a0, br[0], br[1]);
                mma16(acc1[1][2 * j],     a1, br[0], br[1]);
                mma16(acc1[0][2 * j + 1], a0, br[2], br[3]);
                mma16(acc1[1][2 * j + 1], a1, br[2], br[3]);
                ldsm4t(br, b3S + bo);
                mma16(acc3[0][2 * j],     a0, br[0], br[1]);
                mma16(acc3[1][2 * j],     a1, br[0], br[1]);
                mma16(acc3[0][2 * j + 1], a0, br[2], br[3]);
                mma16(acc3[1][2 * j + 1], a1, br[2], br[3]);
            }
        }
    }

    // epilogue: G = silu(D1) * D3 -> fp16
    #pragma unroll
    for (int mt = 0; mt < 2; mt++) {
        int r0 = wm + mt * 16 + g;
        int r1 = r0 + 8;
        bool ok0 = (m0 + r0) < cnt, ok1 = (m0 + r1) < cnt;
        __half* G0 = g_act + ((size_t)e * NTOK + m0 + r0) * IDIM + n0;
        __half* G1 = g_act + ((size_t)e * NTOK + m0 + r1) * IDIM + n0;
        #pragma unroll
        for (int nt = 0; nt < 4; nt++) {
            int cc = wn + nt * 8 + 2 * t;
            if (ok0) {
                float v0 = acc1[mt][nt][0], v1 = acc1[mt][nt][1];
                float o0 = v0 / (1.0f + __expf(-v0)) * acc3[mt][nt][0];
                float o1 = v1 / (1.0f + __expf(-v1)) * acc3[mt][nt][1];
                *(__half2*)(G0 + cc) = __floats2half2_rn(o0, o1);
            }
            if (ok1) {
                float v2 = acc1[mt][nt][2], v3 = acc1[mt][nt][3];
                float o2 = v2 / (1.0f + __expf(-v2)) * acc3[mt][nt][2];
                float o3 = v3 / (1.0f + __expf(-v3)) * acc3[mt][nt][3];
                *(__half2*)(G1 + cc) = __floats2half2_rn(o2, o3);
            }
        }
    }
}

// ---------------------------------------------------------------------------
// FFN2: CTA 128(M)x256(N)xK32, 512 thr (16 warps, 4Mx4N), warp 32x64.
// A = g_act (fp16), B = w2 (fp32->fp16 at STS). P = wt*(G.w2).
// ---------------------------------------------------------------------------
__global__ __launch_bounds__(512)
void ffn2_mma(const float* __restrict__ w2) {
    extern __shared__ __half smh[];
    __shared__ float wts[128];
    const int tid = threadIdx.x;
    const int e   = blockIdx.z;
    const int cnt = g_cnt[e];
    const int m0  = blockIdx.y * 128;
    if (m0 >= cnt) return;
    const int n0  = blockIdx.x * 256;

    if (tid < 128) {
        int r = m0 + tid;
        wts[tid] = (r < cnt) ? g_wt[e][r] : 0.0f;
    }
    __syncthreads();
    const uint32_t sb = smem_u32(smh);
    const uint32_t oB = 2 * A_H * 2;   // [A s0][A s1][B s0][B s1]

    // staging: A fp16 2 uint2/thread, B fp32 4 float4/thread
    const int fa = tid & 7,  ra = tid >> 3;
    const int fb = tid & 63, kb = tid >> 6;   // kb 0..7
    const __half* ga = g_act + ((size_t)e * NTOK + m0) * IDIM;
    const __half* ap0 = ga + (size_t)ra * IDIM + fa * 4;
    const __half* ap1 = ga + (size_t)(ra + 64) * IDIM + fa * 4;
    const float* Wb = w2 + (size_t)e * IDIM * HDIM + n0 + fb * 4;
    const uint32_t dA0 = (ra * AP + fa * 4) * 2;
    const uint32_t dA1 = ((ra + 64) * AP + fa * 4) * 2;
    uint32_t dB[4];
    #pragma unroll
    for (int s = 0; s < 4; s++) dB[s] = ((kb + 8 * s) * BP2 + fb * 4) * 2;

    const int wid = tid >> 5, lane = tid & 31;
    const int wm = (wid >> 2) * 32, wn = (wid & 3) * 64;
    const int g = lane >> 2, t = lane & 3;
    const int rowoff = (lane & 8) + (lane & 7);
    const int khalf  = (lane & 16) >> 1;

    float acc[2][8][4];
    #pragma unroll
    for (int i = 0; i < 2; i++)
        #pragma unroll
        for (int j = 0; j < 8; j++)
            #pragma unroll
            for (int c = 0; c < 4; c++) acc[i][j][c] = 0.f;

    uint2 rA0, rA1;
    float4 rB[4];
    rA0 = *(const uint2*)(ap0);
    rA1 = *(const uint2*)(ap1);
    #pragma unroll
    for (int s = 0; s < 4; s++)
        rB[s] = *(const float4*)(Wb + (size_t)(kb + 8 * s) * HDIM);

    const int NC = IDIM / 32;   // 112
    for (int it = 0; it < NC; it++) {
        int p = it & 1;
        uint32_t aS = sb + p * (A_H * 2);
        uint32_t bS = sb + oB + p * (B2_H * 2);
        sts_u2(aS + dA0, rA0);
        sts_u2(aS + dA1, rA1);
        #pragma unroll
        for (int s = 0; s < 4; s++) sts_h4(bS + dB[s], rB[s]);
        __syncthreads();
        if (it + 1 < NC) {
            int k0 = (it + 1) * 32;
            rA0 = *(const uint2*)(ap0 + k0);
            rA1 = *(const uint2*)(ap1 + k0);
            #pragma unroll
            for (int s = 0; s < 4; s++)
                rB[s] = *(const float4*)(Wb + (size_t)(k0 + kb + 8 * s) * HDIM);
        }
        #pragma unroll
        for (int ks = 0; ks < 2; ks++) {
            uint32_t a0[4], a1[4];
            ldsm4(a0, aS + ((wm + rowoff) * AP + ks * 16 + khalf) * 2);
            ldsm4(a1, aS + ((wm + 16 + rowoff) * AP + ks * 16 + khalf) * 2);
            #pragma unroll
            for (int j = 0; j < 4; j++) {
                uint32_t br[4];
                ldsm4t(br, bS + ((ks * 16 + rowoff) * BP2 + wn + j * 16 + khalf) * 2);
                mma16(acc[0][2 * j],     a0, br[0], br[1]);
                mma16(acc[1][2 * j],     a1, br[0], br[1]);
                mma16(acc[0][2 * j + 1], a0, br[2], br[3]);
                mma16(acc[1][2 * j + 1], a1, br[2], br[3]);
            }
        }
    }

    #pragma unroll
    for (int mt = 0; mt < 2; mt++) {
        int r0 = wm + mt * 16 + g;
        int r1 = r0 + 8;
        bool ok0 = (m0 + r0) < cnt, ok1 = (m0 + r1) < cnt;
        float w0 = wts[r0], w1v = wts[r1];
        float* P0 = g_part + ((size_t)e * NTOK + m0 + r0) * HDIM + n0;
        float* P1 = g_part + ((size_t)e * NTOK + m0 + r1) * HDIM + n0;
        #pragma unroll
        for (int nt = 0; nt < 8; nt++) {
            int cc = wn + nt * 8 + 2 * t;
            if (ok0) *(float2*)(P0 + cc) = make_float2(w0 * acc[mt][nt][0], w0 * acc[mt][nt][1]);
            if (ok1) *(float2*)(P1 + cc) = make_float2(w1v * acc[mt][nt][2], w1v * acc[mt][nt][3]);
        }
    }
}

// ---------------------------------------------------------------------------
__global__ void combine_kernel(float* __restrict__ out) {
    int t  = blockIdx.x;
    int e0 = g_texp[2 * t],     s0 = g_tslot[2 * t];
    int e1 = g_texp[2 * t + 1], s1 = g_tslot[2 * t + 1];
    const float4* P0 = (const float4*)(g_part + ((size_t)e0 * NTOK + s0) * HDIM);
    const float4* P1 = (const float4*)(g_part + ((size_t)e1 * NTOK + s1) * HDIM);
    float4* O = (float4*)(out + (size_t)t * HDIM);
    int i = threadIdx.x;
    float4 a = P0[i], b = P1[i];
    O[i] = make_float4(a.x + b.x, a.y + b.y, a.z + b.z, a.w + b.w);
}

// ---------------------------------------------------------------------------
extern "C" void kernel_launch(void* const* d_in, const int* in_sizes, int n_in,
                              void* d_out, int out_size) {
    const float* x  = (const float*)d_in[0];
    const float* gw = (const float*)d_in[1];
    const float* w1 = (const float*)d_in[2];
    const float* w3 = (const float*)d_in[3];
    const float* w2 = (const float*)d_in[4];
    float* out = (float*)d_out;
    float* logits = out + ((size_t)out_size - (size_t)NTOK * NEXP);

    const int SMEM1 = (2 * A_H + 4 * B1_H) * 2;  // 55296 B
    const int SMEM2 = (2 * A_H + 2 * B2_H) * 2;  // 54272 B
    cudaFuncSetAttribute(ffn1_mma, cudaFuncAttributeMaxDynamicSharedMemorySize, SMEM1);
    cudaFuncSetAttribute(ffn2_mma, cudaFuncAttributeMaxDynamicSharedMemorySize, SMEM2);

    zero_kernel<<<1, 32>>>();
    router_kernel<<<NTOK, 256>>>(x, gw, logits);

    dim3 g1(IDIM / 128, NTOK / 128, NEXP);
    ffn1_mma<<<g1, 512, SMEM1>>>(x, w1, w3);

    dim3 g2(HDIM / 256, NTOK / 128, NEXP);
    ffn2_mma<<<g2, 512, SMEM2>>>(w2);

    combine_kernel<<<NTOK, 256>>>(out);
}